// round 8
// baseline (speedup 1.0000x reference)
#include <cuda_runtime.h>
#include <cuda_fp16.h>
#include <math.h>
#include <stdint.h>

#define B_AG 32768
#define DID  512
#define HID  1024
#define NOPT 8
#define NACT 16

#define MT    64           // agents per CTA
#define NTILE 128          // hidden cols per tile
#define KCH   32           // K per chunk (halves)
#define NCH   (DID/KCH)    // 16
#define NT    128

// ---- smem byte layout ----
// stage s: A_hi[64x80B] A_lo[64x80B] B_hi[128x80B] B_lo[128x80B]
#define A_HI 0
#define A_LO 5120
#define B_HI 10240
#define B_LO 20480
#define STAGE_BYTES 30720
#define ST_OFF(s)  (1024 + (s)*STAGE_BYTES)
// h fp16 planes (64 rows x 128 halves, 272B stride) alias the stage area
// (valid only between stage_h and head_mma, when stages are idle)
#define H_HI 1024
#define H_LO 18432          // 1024 + 64*272
#define HSTR 272
// head-weight fp16 planes (32 n-rows x 128 halves, 272B stride), dedicated
#define HW_HI 62464         // 1024 + 2*30720
#define HW_LO 71168         // + 32*272
// final staging aliases the headW region (written after last head_mma)
#define FIN0_OFFB 62464
#define FIN1_OFFB 70912     // + 64*33*4
#define FINSTR 33
#define BIAS_OFFB 79872
#define MISC_OFFB 80384
#define SMEM_BYTES 81152    // x2 CTAs = 162304 < 228KB

__device__ int    g_opt_cnt[NOPT];
__device__ int    g_opt_list[NOPT*B_AG];
__device__ __half g_obsHi[(size_t)B_AG*DID];
__device__ __half g_obsLo[(size_t)B_AG*DID];
__device__ __half g_wHiT[(size_t)10*HID*DID];   // K-major: [mat][h][k]
__device__ __half g_wLoT[(size_t)10*HID*DID];

// ---------------------------------------------------------------------------
// PTX helpers (baseline PTX only: cp.async / ldmatrix / mma.sync)
// ---------------------------------------------------------------------------
__device__ __forceinline__ void cp16(uint32_t dst, const void* src) {
    asm volatile("cp.async.cg.shared.global [%0], [%1], 16;" :: "r"(dst), "l"(src));
}
#define CP_COMMIT() asm volatile("cp.async.commit_group;")

__device__ __forceinline__ void ldm4(uint32_t a, uint32_t r[4]) {
    asm volatile("ldmatrix.sync.aligned.m8n8.x4.shared.b16 {%0,%1,%2,%3}, [%4];"
        : "=r"(r[0]), "=r"(r[1]), "=r"(r[2]), "=r"(r[3]) : "r"(a));
}
__device__ __forceinline__ void mma16816(float d[4], const uint32_t a[4],
                                         uint32_t b0, uint32_t b1) {
    asm volatile("mma.sync.aligned.m16n8k16.row.col.f32.f16.f16.f32 "
        "{%0,%1,%2,%3}, {%4,%5,%6,%7}, {%8,%9}, {%0,%1,%2,%3};"
        : "+f"(d[0]), "+f"(d[1]), "+f"(d[2]), "+f"(d[3])
        : "r"(a[0]), "r"(a[1]), "r"(a[2]), "r"(a[3]), "r"(b0), "r"(b1));
}

// ---------------------------------------------------------------------------
// Convert kernels (one-time per launch)
// ---------------------------------------------------------------------------
__global__ void __launch_bounds__(256)
convert_obs_kernel(const float* __restrict__ obs) {
    size_t i = ((size_t)blockIdx.x*256 + threadIdx.x)*8;
    float v[8]; __half hi[8], lo[8];
    #pragma unroll
    for (int k = 0; k < 8; ++k) v[k] = obs[i + k];
    #pragma unroll
    for (int k = 0; k < 8; ++k) {
        hi[k] = __float2half_rn(v[k]);
        lo[k] = __float2half_rn(v[k] - __half2float(hi[k]));
    }
    *(uint4*)&g_obsHi[i] = *(uint4*)hi;
    *(uint4*)&g_obsLo[i] = *(uint4*)lo;
    if (blockIdx.x == 0 && threadIdx.x < NOPT) g_opt_cnt[threadIdx.x] = 0;
}

__global__ void __launch_bounds__(256)
convert_w_kernel(const float* __restrict__ Wm1,
                 const float* __restrict__ Wt1,
                 const float* __restrict__ W1) {
    __shared__ float tile[32][33];
    const int m = blockIdx.z;
    const float* src = (m == 0) ? Wm1 : (m == 1) ? Wt1 : W1 + (size_t)(m-2)*DID*HID;
    const int h0 = blockIdx.x * 32;
    const int k0 = blockIdx.y * 32;
    const int tx = threadIdx.x, ty0 = threadIdx.y;
    #pragma unroll
    for (int r = 0; r < 32; r += 8)
        tile[r + ty0][tx] = src[(size_t)(k0 + r + ty0)*HID + h0 + tx];
    __syncthreads();
    __half* dHi = g_wHiT + (size_t)m*HID*DID;
    __half* dLo = g_wLoT + (size_t)m*HID*DID;
    #pragma unroll
    for (int r = 0; r < 32; r += 8) {
        float x = tile[tx][r + ty0];
        __half hi = __float2half_rn(x);
        __half lo = __float2half_rn(x - __half2float(hi));
        size_t o = (size_t)(h0 + r + ty0)*DID + k0 + tx;
        dHi[o] = hi; dLo[o] = lo;
    }
}

// ---------------------------------------------------------------------------
// Core GEMM tile: [64 x 128] over K=512, fp16 hi/lo 3-pass into f32 acc.
// 4 warps: wm=(w&1)*32, wn=(w>>1)*64; warp tile 32x64. Ends synced.
// ---------------------------------------------------------------------------
__device__ __forceinline__ void gemm_tile(uint32_t su, int t,
    const __half* aHi0, const __half* aHi1,
    const __half* aLo0, const __half* aLo1,
    const __half* bHi,  const __half* bLo,
    float acc[2][8][4])
{
    const int lane = t & 31, w = t >> 5;
    const int wm = (w & 1) * 32, wn = (w >> 1) * 64;
    const uint32_t drow = (uint32_t)((t >> 2)*80 + (t & 3)*16);

    #define FILL(s, kc) do {                                    \
        uint32_t _b = su + ST_OFF(s) + drow;                    \
        const int _ko = (kc)*KCH;                               \
        cp16(_b + A_HI,        aHi0 + _ko);                     \
        cp16(_b + A_HI + 2560, aHi1 + _ko);                     \
        cp16(_b + A_LO,        aLo0 + _ko);                     \
        cp16(_b + A_LO + 2560, aLo1 + _ko);                     \
        _Pragma("unroll")                                       \
        for (int _i = 0; _i < 4; ++_i) {                        \
            cp16(_b + B_HI + _i*2560, bHi + _i*32*DID + _ko);   \
            cp16(_b + B_LO + _i*2560, bLo + _i*32*DID + _ko);   \
        }                                                       \
        CP_COMMIT();                                            \
    } while (0)

    FILL(0, 0);

    #pragma unroll 1
    for (int kc = 0; kc < NCH; ++kc) {
        const int cur = kc & 1;
        if (kc + 1 < NCH) {
            FILL(cur ^ 1, kc + 1);
            asm volatile("cp.async.wait_group 1;");
        } else {
            asm volatile("cp.async.wait_group 0;");
        }
        __syncthreads();

        const uint32_t sb = su + ST_OFF(cur);
        #pragma unroll
        for (int ks = 0; ks < 2; ++ks) {
            const uint32_t ko = ks*32 + (lane >> 4)*16;
            const uint32_t aadr = sb + A_HI + (uint32_t)((wm + (lane & 15))*80) + ko;
            uint32_t ah0[4], ah1[4], al0[4], al1[4];
            ldm4(aadr,          ah0);
            ldm4(aadr + 16*80,  ah1);
            ldm4(aadr + 5120,         al0);
            ldm4(aadr + 5120 + 16*80, al1);

            uint32_t bh[4][4], bl[4][4];
            #pragma unroll
            for (int j = 0; j < 4; ++j) {
                const uint32_t badr = sb + B_HI
                    + (uint32_t)((wn + j*16 + (lane & 15))*80) + ko;
                ldm4(badr,         bh[j]);
                ldm4(badr + 10240, bl[j]);
            }

            #pragma unroll
            for (int j = 0; j < 4; ++j) {
                mma16816(acc[0][2*j  ], ah0, bh[j][0], bh[j][2]);
                mma16816(acc[0][2*j+1], ah0, bh[j][1], bh[j][3]);
                mma16816(acc[1][2*j  ], ah1, bh[j][0], bh[j][2]);
                mma16816(acc[1][2*j+1], ah1, bh[j][1], bh[j][3]);
            }
            #pragma unroll
            for (int j = 0; j < 4; ++j) {
                mma16816(acc[0][2*j  ], ah0, bl[j][0], bl[j][2]);
                mma16816(acc[0][2*j+1], ah0, bl[j][1], bl[j][3]);
                mma16816(acc[1][2*j  ], ah1, bl[j][0], bl[j][2]);
                mma16816(acc[1][2*j+1], ah1, bl[j][1], bl[j][3]);
            }
            #pragma unroll
            for (int j = 0; j < 4; ++j) {
                mma16816(acc[0][2*j  ], al0, bh[j][0], bh[j][2]);
                mma16816(acc[0][2*j+1], al0, bh[j][1], bh[j][3]);
                mma16816(acc[1][2*j  ], al1, bh[j][0], bh[j][2]);
                mma16816(acc[1][2*j+1], al1, bh[j][1], bh[j][3]);
            }
        }
        __syncthreads();
    }
    #undef FILL
}

// relu(acc + bias) -> fp16 hi/lo h planes (alias idle stage smem)
__device__ __forceinline__ void stage_h(float* smf, const float acc[2][8][4],
                                        int t) {
    const int lane = t & 31, w = t >> 5;
    const int wm = (w & 1) * 32, wn = (w >> 1) * 64;
    char* base = (char*)smf;
    const float* bias_s = smf + BIAS_OFFB/4;
    #pragma unroll
    for (int im = 0; im < 2; ++im) {
        #pragma unroll
        for (int j = 0; j < 8; ++j) {
            #pragma unroll
            for (int ep = 0; ep < 2; ++ep) {
                int row = wm + im*16 + (lane >> 2) + ep*8;
                int col = wn + j*8 + 2*(lane & 3);
                float x0 = fmaxf(acc[im][j][2*ep]   + bias_s[col],     0.f);
                float x1 = fmaxf(acc[im][j][2*ep+1] + bias_s[col + 1], 0.f);
                __half h0 = __float2half_rn(x0);
                __half h1 = __float2half_rn(x1);
                __half l0 = __float2half_rn(x0 - __half2float(h0));
                __half l1 = __float2half_rn(x1 - __half2float(h1));
                *(__half2*)(base + H_HI + row*HSTR + col*2) = __halves2half2(h0, h1);
                *(__half2*)(base + H_LO + row*HSTR + col*2) = __halves2half2(l0, l1);
            }
        }
    }
}

// head-GEMM: h[64x128] @ headW^T[128x32], 3-pass hi/lo, per-warp n8 slice.
__device__ __forceinline__ void head_mma(uint32_t su, int t, float hacc[4][4]) {
    const int lane = t & 31, w = t >> 5;
    const uint32_t arow = su + H_HI + (uint32_t)((lane & 15)*HSTR) + (lane >> 4)*16;
    const uint32_t brow = su + HW_HI
        + (uint32_t)(((w >> 1)*16 + (lane & 15))*HSTR) + (lane >> 4)*16;
    const int sel = w & 1;
    #pragma unroll
    for (int k16 = 0; k16 < 8; ++k16) {
        const uint32_t ko = k16*32;
        uint32_t bh[4], bl[4];
        ldm4(brow + ko, bh);
        ldm4(brow + ko + (HW_LO - HW_HI), bl);
        const uint32_t b0h = sel ? bh[1] : bh[0], b1h = sel ? bh[3] : bh[2];
        const uint32_t b0l = sel ? bl[1] : bl[0], b1l = sel ? bl[3] : bl[2];
        #pragma unroll
        for (int m = 0; m < 4; ++m) {
            uint32_t ah[4], al[4];
            ldm4(arow + m*16*HSTR + ko, ah);
            ldm4(arow + m*16*HSTR + ko + (H_LO - H_HI), al);
            mma16816(hacc[m], ah, b0h, b1h);
            mma16816(hacc[m], ah, b0l, b1l);
            mma16816(hacc[m], al, b0h, b1h);
        }
    }
}

// store per-warp head acc into fin staging
__device__ __forceinline__ void store_hacc(float* fin, int t,
                                           const float hacc[4][4]) {
    const int lane = t & 31, w = t >> 5;
    const int n0 = (w >> 1)*16 + (w & 1)*8;
    #pragma unroll
    for (int m = 0; m < 4; ++m) {
        #pragma unroll
        for (int e = 0; e < 4; ++e) {
            int row = m*16 + (lane >> 2) + 8*(e >> 1);
            int col = n0 + 2*(lane & 3) + (e & 1);
            fin[row*FINSTR + col] = hacc[m][e];
        }
    }
}

// zero headW plane rows 17..31 (once per kernel)
__device__ __forceinline__ void zero_hw_tail(char* base, int t) {
    for (int i = t; i < 15*68; i += NT) {
        int row = 17 + i/68, wd = i % 68;
        *(uint32_t*)(base + HW_HI + row*HSTR + wd*4) = 0u;
        *(uint32_t*)(base + HW_LO + row*HSTR + wd*4) = 0u;
    }
}

__device__ __forceinline__ void put_hw(char* base, int o, int t, float v) {
    __half hi = __float2half_rn(v);
    __half lo = __float2half_rn(v - __half2float(hi));
    *(__half*)(base + HW_HI + o*HSTR + t*2) = hi;
    *(__half*)(base + HW_LO + o*HSTR + t*2) = lo;
}

// ---------------------------------------------------------------------------
// Phase A: fused meta + termination nets.
// ---------------------------------------------------------------------------
__global__ void __launch_bounds__(NT, 2)
phaseA_kernel(const int*   __restrict__ dones,
              const int*   __restrict__ exec_opt,
              const float* __restrict__ bm1,
              const float* __restrict__ Wm_pi,
              const float* __restrict__ Wm_v,
              const float* __restrict__ Wt2,
              float* __restrict__ out)
{
    extern __shared__ float smf[];
    char* base = (char*)smf;
    const uint32_t su = (uint32_t)__cvta_generic_to_shared(smf);
    const int t = threadIdx.x;
    const int g0 = blockIdx.x * MT;

    float* bias_s = smf + BIAS_OFFB/4;
    int*   icnt   = (int*)(base + MISC_OFFB);

    zero_hw_tail(base, t);

    const size_t arow = (size_t)(g0 + (t >> 2))*DID + (t & 3)*8;
    const __half* aHi0 = g_obsHi + arow;
    const __half* aHi1 = aHi0 + (size_t)32*DID;
    const __half* aLo0 = g_obsLo + arow;
    const __half* aLo1 = aLo0 + (size_t)32*DID;

    float hacc0[4][4], hacc1[4][4];
    #pragma unroll
    for (int m = 0; m < 4; ++m)
        #pragma unroll
        for (int e = 0; e < 4; ++e) { hacc0[m][e] = 0.f; hacc1[m][e] = 0.f; }

    #pragma unroll 1
    for (int net = 0; net < 2; ++net) {
        #pragma unroll 1
        for (int ht = 0; ht < HID/NTILE; ++ht) {
            const int hbase = ht * NTILE;
            // per-tile: bias + head weights -> fp16 hi/lo planes (col = t)
            if (net == 0) {
                bias_s[t] = bm1[hbase + t];
                const float* wp = Wm_pi + (size_t)(hbase + t)*NOPT;
                #pragma unroll
                for (int o = 0; o < 8; ++o) put_hw(base, o, t, wp[o]);
                put_hw(base, 8, t, Wm_v[hbase + t]);
                #pragma unroll
                for (int o = 9; o < 17; ++o) put_hw(base, o, t, 0.f);
            } else {
                bias_s[t] = 0.f;
                const float* wp = Wt2 + (size_t)(hbase + t)*NOPT;
                #pragma unroll
                for (int o = 0; o < 8; ++o) put_hw(base, o, t, wp[o]);
                #pragma unroll
                for (int o = 8; o < 17; ++o) put_hw(base, o, t, 0.f);
            }
            const size_t brow = ((size_t)net*HID + hbase + (t >> 2))*DID + (t & 3)*8;

            float acc[2][8][4];
            #pragma unroll
            for (int i = 0; i < 2; ++i)
                #pragma unroll
                for (int j = 0; j < 8; ++j)
                    #pragma unroll
                    for (int e = 0; e < 4; ++e) acc[i][j][e] = 0.f;

            gemm_tile(su, t, aHi0, aHi1, aLo0, aLo1,
                      g_wHiT + brow, g_wLoT + brow, acc);
            stage_h(smf, acc, t);
            __syncthreads();
            head_mma(su, t, net == 0 ? hacc0 : hacc1);
            __syncthreads();
        }
    }

    store_hacc((float*)(base + FIN0_OFFB), t, hacc0);
    store_hacc((float*)(base + FIN1_OFFB), t, hacc1);

    int* s_cnt  = icnt + 64;
    int* s_base = icnt + 72;
    if (t < NOPT) s_cnt[t] = 0;
    __syncthreads();

    int myno = 0, mypos = 0;
    if (t < MT) {
        const float* fin0 = (const float*)(base + FIN0_OFFB) + t*FINSTR;
        const float* fin1 = (const float*)(base + FIN1_OFFB) + t*FINSTR;
        const int g = g0 + t;
        float lg[8];
        #pragma unroll
        for (int o = 0; o < 8; ++o) lg[o] = fin0[o];
        float mv = fin0[8];
        float m = lg[0]; int am = 0;
        #pragma unroll
        for (int o = 1; o < 8; ++o) if (lg[o] > m) { m = lg[o]; am = o; }
        float s = 0.f;
        #pragma unroll
        for (int o = 0; o < 8; ++o) s += expf(lg[o] - m);
        float lp = -logf(s);
        int eo = exec_opt[g];
        float tl = fin1[eo];
        float tp = 1.0f/(1.0f + expf(-tl));
        bool dn = (dones[g] != 0);
        bool term = dn || (tp > 0.5f);
        myno = term ? am : eo;
        out[3*B_AG + g] = (float)am;
        out[4*B_AG + g] = mv;
        out[5*B_AG + g] = lp;
        out[6*B_AG + g] = tp;
        mypos = atomicAdd(&s_cnt[myno], 1);
    }
    __syncthreads();
    if (t < NOPT) s_base[t] = atomicAdd(&g_opt_cnt[t], s_cnt[t]);
    __syncthreads();
    if (t < MT) g_opt_list[myno*B_AG + s_base[myno] + mypos] = g0 + t;
}

// ---------------------------------------------------------------------------
// Phase B: per-option sub-policy on compacted lists.
// ---------------------------------------------------------------------------
__global__ void __launch_bounds__(NT, 2)
phaseB_kernel(const float* __restrict__ b1,
              const float* __restrict__ Wpi,
              const float* __restrict__ Wv,
              float* __restrict__ out)
{
    const int opt   = blockIdx.y;
    const int start = blockIdx.x * MT;
    const int cnt   = g_opt_cnt[opt];
    if (start >= cnt) return;
    const int nvalid = min(MT, cnt - start);

    extern __shared__ float smf[];
    char* base = (char*)smf;
    const uint32_t su = (uint32_t)__cvta_generic_to_shared(smf);
    const int t = threadIdx.x;

    float* bias_s = smf + BIAS_OFFB/4;
    int*   idx_s  = (int*)(base + MISC_OFFB);

    zero_hw_tail(base, t);

    if (t < MT) {
        int src = opt*B_AG + start + ((t < nvalid) ? t : 0);
        idx_s[t] = g_opt_list[src];
    }
    __syncthreads();

    const size_t arow0 = (size_t)idx_s[t >> 2]*DID + (t & 3)*8;
    const size_t arow1 = (size_t)idx_s[(t >> 2) + 32]*DID + (t & 3)*8;
    const __half* aHi0 = g_obsHi + arow0;
    const __half* aHi1 = g_obsHi + arow1;
    const __half* aLo0 = g_obsLo + arow0;
    const __half* aLo1 = g_obsLo + arow1;

    const float* bg   = b1  + (size_t)opt*HID;
    const float* wpig = Wpi + (size_t)opt*HID*NACT;
    const float* wvg  = Wv  + (size_t)opt*HID;

    float hacc[4][4];
    #pragma unroll
    for (int m = 0; m < 4; ++m)
        #pragma unroll
        for (int e = 0; e < 4; ++e) hacc[m][e] = 0.f;

    #pragma unroll 1
    for (int ht = 0; ht < HID/NTILE; ++ht) {
        const int hbase = ht * NTILE;
        bias_s[t] = bg[hbase + t];
        {
            const float* wp = wpig + (size_t)(hbase + t)*NACT;
            #pragma unroll
            for (int a = 0; a < NACT; ++a) put_hw(base, a, t, wp[a]);
            put_hw(base, 16, t, wvg[hbase + t]);
        }
        const size_t brow = ((size_t)(2 + opt)*HID + hbase + (t >> 2))*DID + (t & 3)*8;

        float acc[2][8][4];
        #pragma unroll
        for (int i = 0; i < 2; ++i)
            #pragma unroll
            for (int j = 0; j < 8; ++j)
                #pragma unroll
                for (int e = 0; e < 4; ++e) acc[i][j][e] = 0.f;

        gemm_tile(su, t, aHi0, aHi1, aLo0, aLo1,
                  g_wHiT + brow, g_wLoT + brow, acc);
        stage_h(smf, acc, t);
        __syncthreads();
        head_mma(su, t, hacc);
        __syncthreads();
    }

    store_hacc((float*)(base + FIN0_OFFB), t, hacc);
    __syncthreads();

    if (t < MT && t < nvalid) {
        const float* fin = (const float*)(base + FIN0_OFFB) + t*FINSTR;
        const int g = idx_s[t];
        float lg[16];
        #pragma unroll
        for (int a = 0; a < NACT; ++a) lg[a] = fin[a];
        float val = fin[16];
        float m = lg[0]; int am = 0;
        #pragma unroll
        for (int a = 1; a < NACT; ++a) if (lg[a] > m) { m = lg[a]; am = a; }
        float s = 0.f;
        #pragma unroll
        for (int a = 0; a < NACT; ++a) s += expf(lg[a] - m);
        float lp = -logf(s);
        out[          g] = (float)am;
        out[  B_AG +  g] = val;
        out[2*B_AG +  g] = lp;
    }
}

extern "C" void kernel_launch(void* const* d_in, const int* in_sizes, int n_in,
                              void* d_out, int out_size) {
    const float* obs      = (const float*)d_in[0];
    const int*   dones    = (const int*)  d_in[1];
    const int*   exec_opt = (const int*)  d_in[2];
    const float* Wm1      = (const float*)d_in[3];
    const float* bm1      = (const float*)d_in[4];
    const float* Wm_pi    = (const float*)d_in[5];
    const float* Wm_v     = (const float*)d_in[6];
    const float* Wt1      = (const float*)d_in[7];
    const float* Wt2      = (const float*)d_in[8];
    const float* W1       = (const float*)d_in[9];
    const float* b1       = (const float*)d_in[10];
    const float* Wpi      = (const float*)d_in[11];
    const float* Wv       = (const float*)d_in[12];
    float* out = (float*)d_out;

    cudaFuncSetAttribute(phaseA_kernel,
                         cudaFuncAttributeMaxDynamicSharedMemorySize, SMEM_BYTES);
    cudaFuncSetAttribute(phaseB_kernel,
                         cudaFuncAttributeMaxDynamicSharedMemorySize, SMEM_BYTES);

    convert_obs_kernel<<<(B_AG*DID)/(256*8), 256>>>(obs);
    dim3 gW(HID/32, DID/32, 10);
    convert_w_kernel<<<gW, dim3(32, 8)>>>(Wm1, Wt1, W1);
    phaseA_kernel<<<B_AG/MT, NT, SMEM_BYTES>>>(
        dones, exec_opt, bm1, Wm_pi, Wm_v, Wt2, out);
    dim3 gB(B_AG/MT, NOPT);
    phaseB_kernel<<<gB, NT, SMEM_BYTES>>>(b1, Wpi, Wv, out);
}

// round 9
// speedup vs baseline: 1.0061x; 1.0061x over previous
#include <cuda_runtime.h>
#include <cuda_fp16.h>
#include <math.h>
#include <stdint.h>

#define B_AG 32768
#define DID  512
#define HID  1024
#define NOPT 8
#define NACT 16

#define MT    64
#define NTILE 128
#define KCH   32
#define NCH   16
#define NT    128

// ---- smem byte layout (NO aliasing between stages and H/HW) ----
#define ST(s)   ((s)*30720)        // stage: A_hi 5120 | A_lo 5120 | B_hi 10240 | B_lo 10240
#define A_HI 0
#define A_LO 5120
#define B_HI 10240
#define B_LO 20480
#define H_HI  61440                // 64 x 272B
#define H_LO  78848
#define HSTR  272
#define HW_HI 96256                // 32 x 272B
#define HW_LO 104960
#define BIAS_OFFB 113664           // 128 floats
#define MISC_OFFB 114176
#define SMEM_BYTES 114688          // x2 = 229376 <= 233472
#define FIN0_OFFB 61440            // alias H_HI (after last head_mma)
#define FIN1_OFFB 78848            // alias H_LO
#define FINSTR 33

__device__ int    g_opt_cnt[NOPT];
__device__ int    g_opt_list[NOPT*B_AG];
__device__ __half g_obsHi[(size_t)B_AG*DID];
__device__ __half g_obsLo[(size_t)B_AG*DID];
__device__ __half g_wHiT[(size_t)10*HID*DID];
__device__ __half g_wLoT[(size_t)10*HID*DID];

// ---------------------------------------------------------------------------
__device__ __forceinline__ void cp16(uint32_t dst, const void* src) {
    asm volatile("cp.async.cg.shared.global [%0], [%1], 16;" :: "r"(dst), "l"(src));
}
#define CP_COMMIT() asm volatile("cp.async.commit_group;")
#define CP_WAIT0()  asm volatile("cp.async.wait_group 0;")

__device__ __forceinline__ void ldm4(uint32_t a, uint32_t r[4]) {
    asm volatile("ldmatrix.sync.aligned.m8n8.x4.shared.b16 {%0,%1,%2,%3}, [%4];"
        : "=r"(r[0]), "=r"(r[1]), "=r"(r[2]), "=r"(r[3]) : "r"(a));
}
__device__ __forceinline__ void mma16816(float d[4], const uint32_t a[4],
                                         uint32_t b0, uint32_t b1) {
    asm volatile("mma.sync.aligned.m16n8k16.row.col.f32.f16.f16.f32 "
        "{%0,%1,%2,%3}, {%4,%5,%6,%7}, {%8,%9}, {%0,%1,%2,%3};"
        : "+f"(d[0]), "+f"(d[1]), "+f"(d[2]), "+f"(d[3])
        : "r"(a[0]), "r"(a[1]), "r"(a[2]), "r"(a[3]), "r"(b0), "r"(b1));
}

// ---------------------------------------------------------------------------
__global__ void __launch_bounds__(256)
convert_obs_kernel(const float* __restrict__ obs) {
    size_t i = ((size_t)blockIdx.x*256 + threadIdx.x)*8;
    float v[8]; __half hi[8], lo[8];
    #pragma unroll
    for (int k = 0; k < 8; ++k) v[k] = obs[i + k];
    #pragma unroll
    for (int k = 0; k < 8; ++k) {
        hi[k] = __float2half_rn(v[k]);
        lo[k] = __float2half_rn(v[k] - __half2float(hi[k]));
    }
    *(uint4*)&g_obsHi[i] = *(uint4*)hi;
    *(uint4*)&g_obsLo[i] = *(uint4*)lo;
    if (blockIdx.x == 0 && threadIdx.x < NOPT) g_opt_cnt[threadIdx.x] = 0;
}

__global__ void __launch_bounds__(256)
convert_w_kernel(const float* __restrict__ Wm1,
                 const float* __restrict__ Wt1,
                 const float* __restrict__ W1) {
    __shared__ float tile[32][33];
    const int m = blockIdx.z;
    const float* src = (m == 0) ? Wm1 : (m == 1) ? Wt1 : W1 + (size_t)(m-2)*DID*HID;
    const int h0 = blockIdx.x * 32;
    const int k0 = blockIdx.y * 32;
    const int tx = threadIdx.x, ty0 = threadIdx.y;
    #pragma unroll
    for (int r = 0; r < 32; r += 8)
        tile[r + ty0][tx] = src[(size_t)(k0 + r + ty0)*HID + h0 + tx];
    __syncthreads();
    __half* dHi = g_wHiT + (size_t)m*HID*DID;
    __half* dLo = g_wLoT + (size_t)m*HID*DID;
    #pragma unroll
    for (int r = 0; r < 32; r += 8) {
        float x = tile[tx][r + ty0];
        __half hi = __float2half_rn(x);
        __half lo = __float2half_rn(x - __half2float(hi));
        size_t o = (size_t)(h0 + r + ty0)*DID + k0 + tx;
        dHi[o] = hi; dLo[o] = lo;
    }
}

// ---------------------------------------------------------------------------
// fill chunk g's data into stage g&1. bT = B-tile base (row 0 of this tile),
// already including matrix/net/option offset.
// ---------------------------------------------------------------------------
__device__ __forceinline__ void fill_chunk(uint32_t su, int t, int g,
    const __half* aHi, const __half* aLo,
    const __half* bHiT, const __half* bLoT)
{
    const uint32_t drow = (uint32_t)((t >> 2)*80 + (t & 3)*16);
    const uint32_t sb = su + ST(g & 1) + drow;
    const int ko = (g & 15)*KCH;
    cp16(sb + A_HI,        aHi + ko);
    cp16(sb + A_HI + 2560, aHi + 32*DID + ko);
    cp16(sb + A_LO,        aLo + ko);
    cp16(sb + A_LO + 2560, aLo + 32*DID + ko);
    const size_t boff = (size_t)(t >> 2)*DID + (t & 3)*8 + ko;
    #pragma unroll
    for (int j = 0; j < 4; ++j) {
        cp16(sb + B_HI + j*2560, bHiT + boff + j*32*DID);
        cp16(sb + B_LO + j*2560, bLoT + boff + j*32*DID);
    }
    CP_COMMIT();
}

// compute chunk g (stage g&1) into acc — identical math to R8
__device__ __forceinline__ void compute_chunk(uint32_t su, int t, int g,
                                              float acc[2][8][4]) {
    const int lane = t & 31, w = t >> 5;
    const int wm = (w & 1) * 32, wn = (w >> 1) * 64;
    const uint32_t sb = su + ST(g & 1);
    #pragma unroll
    for (int ks = 0; ks < 2; ++ks) {
        const uint32_t ko = ks*32 + (lane >> 4)*16;
        const uint32_t aadr = sb + A_HI + (uint32_t)((wm + (lane & 15))*80) + ko;
        uint32_t ah0[4], ah1[4], al0[4], al1[4];
        ldm4(aadr,          ah0);
        ldm4(aadr + 16*80,  ah1);
        ldm4(aadr + 5120,         al0);
        ldm4(aadr + 5120 + 16*80, al1);
        uint32_t bh[4][4], bl[4][4];
        #pragma unroll
        for (int j = 0; j < 4; ++j) {
            const uint32_t badr = sb + B_HI
                + (uint32_t)((wn + j*16 + (lane & 15))*80) + ko;
            ldm4(badr,         bh[j]);
            ldm4(badr + 10240, bl[j]);
        }
        #pragma unroll
        for (int j = 0; j < 4; ++j) {
            mma16816(acc[0][2*j  ], ah0, bh[j][0], bh[j][2]);
            mma16816(acc[0][2*j+1], ah0, bh[j][1], bh[j][3]);
            mma16816(acc[1][2*j  ], ah1, bh[j][0], bh[j][2]);
            mma16816(acc[1][2*j+1], ah1, bh[j][1], bh[j][3]);
        }
        #pragma unroll
        for (int j = 0; j < 4; ++j) {
            mma16816(acc[0][2*j  ], ah0, bl[j][0], bl[j][2]);
            mma16816(acc[0][2*j+1], ah0, bl[j][1], bl[j][3]);
            mma16816(acc[1][2*j  ], ah1, bl[j][0], bl[j][2]);
            mma16816(acc[1][2*j+1], ah1, bl[j][1], bl[j][3]);
        }
        #pragma unroll
        for (int j = 0; j < 4; ++j) {
            mma16816(acc[0][2*j  ], al0, bh[j][0], bh[j][2]);
            mma16816(acc[0][2*j+1], al0, bh[j][1], bh[j][3]);
            mma16816(acc[1][2*j  ], al1, bh[j][0], bh[j][2]);
            mma16816(acc[1][2*j+1], al1, bh[j][1], bh[j][3]);
        }
    }
}

__device__ __forceinline__ void stage_h(char* base, const float acc[2][8][4],
                                        int t) {
    const int lane = t & 31, w = t >> 5;
    const int wm = (w & 1) * 32, wn = (w >> 1) * 64;
    const float* bias_s = (const float*)(base + BIAS_OFFB);
    #pragma unroll
    for (int im = 0; im < 2; ++im) {
        #pragma unroll
        for (int j = 0; j < 8; ++j) {
            #pragma unroll
            for (int ep = 0; ep < 2; ++ep) {
                int row = wm + im*16 + (lane >> 2) + ep*8;
                int col = wn + j*8 + 2*(lane & 3);
                float x0 = fmaxf(acc[im][j][2*ep]   + bias_s[col],     0.f);
                float x1 = fmaxf(acc[im][j][2*ep+1] + bias_s[col + 1], 0.f);
                __half h0 = __float2half_rn(x0);
                __half h1 = __float2half_rn(x1);
                __half l0 = __float2half_rn(x0 - __half2float(h0));
                __half l1 = __float2half_rn(x1 - __half2float(h1));
                *(__half2*)(base + H_HI + row*HSTR + col*2) = __halves2half2(h0, h1);
                *(__half2*)(base + H_LO + row*HSTR + col*2) = __halves2half2(l0, l1);
            }
        }
    }
}

__device__ __forceinline__ void head_mma(uint32_t su, int t, float hacc[4][4]) {
    const int lane = t & 31, w = t >> 5;
    const uint32_t arow = su + H_HI + (uint32_t)((lane & 15)*HSTR) + (lane >> 4)*16;
    const uint32_t brow = su + HW_HI
        + (uint32_t)(((w >> 1)*16 + (lane & 15))*HSTR) + (lane >> 4)*16;
    const int sel = w & 1;
    #pragma unroll
    for (int k16 = 0; k16 < 8; ++k16) {
        const uint32_t ko = k16*32;
        uint32_t bh[4], bl[4];
        ldm4(brow + ko, bh);
        ldm4(brow + ko + (HW_LO - HW_HI), bl);
        const uint32_t b0h = sel ? bh[1] : bh[0], b1h = sel ? bh[3] : bh[2];
        const uint32_t b0l = sel ? bl[1] : bl[0], b1l = sel ? bl[3] : bl[2];
        #pragma unroll
        for (int m = 0; m < 4; ++m) {
            uint32_t ah[4], al[4];
            ldm4(arow + m*16*HSTR + ko, ah);
            ldm4(arow + m*16*HSTR + ko + (H_LO - H_HI), al);
            mma16816(hacc[m], ah, b0h, b1h);
            mma16816(hacc[m], ah, b0l, b1l);
            mma16816(hacc[m], al, b0h, b1h);
        }
    }
}

__device__ __forceinline__ void store_hacc(float* fin, int t,
                                           const float hacc[4][4]) {
    const int lane = t & 31, w = t >> 5;
    const int n0 = (w >> 1)*16 + (w & 1)*8;
    #pragma unroll
    for (int m = 0; m < 4; ++m) {
        #pragma unroll
        for (int e = 0; e < 4; ++e) {
            int row = m*16 + (lane >> 2) + 8*(e >> 1);
            int col = n0 + 2*(lane & 3) + (e & 1);
            fin[row*FINSTR + col] = hacc[m][e];
        }
    }
}

__device__ __forceinline__ void zero_hw_tail(char* base, int t) {
    for (int i = t; i < 15*68; i += NT) {
        int row = 17 + i/68, wd = i % 68;
        *(uint32_t*)(base + HW_HI + row*HSTR + wd*4) = 0u;
        *(uint32_t*)(base + HW_LO + row*HSTR + wd*4) = 0u;
    }
}
__device__ __forceinline__ void put_hw(char* base, int o, int t, float v) {
    __half hi = __float2half_rn(v);
    __half lo = __float2half_rn(v - __half2float(hi));
    *(__half*)(base + HW_HI + o*HSTR + t*2) = hi;
    *(__half*)(base + HW_LO + o*HSTR + t*2) = lo;
}

#define ZERO_ACC(acc) do {                                 \
    _Pragma("unroll") for (int _i = 0; _i < 2; ++_i)       \
    _Pragma("unroll") for (int _j = 0; _j < 8; ++_j)       \
    _Pragma("unroll") for (int _e = 0; _e < 4; ++_e)       \
        (acc)[_i][_j][_e] = 0.f;                           \
} while (0)

// write head weights + bias for phaseA tile tt (0..15)
__device__ __forceinline__ void loadA_hw(char* base, int t, int tt,
    const float* bm1, const float* Wm_pi, const float* Wm_v,
    const float* Wt2)
{
    const int net = tt >> 3, hbase = (tt & 7)*NTILE;
    float* bias_s = (float*)(base + BIAS_OFFB);
    if (net == 0) {
        const float* wp = Wm_pi + (size_t)(hbase + t)*NOPT;
        #pragma unroll
        for (int o = 0; o < 8; ++o) put_hw(base, o, t, wp[o]);
        put_hw(base, 8, t, Wm_v[hbase + t]);
        #pragma unroll
        for (int o = 9; o < 17; ++o) put_hw(base, o, t, 0.f);
        bias_s[t] = bm1[hbase + t];
    } else {
        const float* wp = Wt2 + (size_t)(hbase + t)*NOPT;
        #pragma unroll
        for (int o = 0; o < 8; ++o) put_hw(base, o, t, wp[o]);
        #pragma unroll
        for (int o = 8; o < 17; ++o) put_hw(base, o, t, 0.f);
        bias_s[t] = 0.f;
    }
}

// ---------------------------------------------------------------------------
// Phase A: continuous 256-chunk stream over (2 nets x 8 tiles x 16 chunks)
// ---------------------------------------------------------------------------
__global__ void __launch_bounds__(NT, 2)
phaseA_kernel(const int*   __restrict__ dones,
              const int*   __restrict__ exec_opt,
              const float* __restrict__ bm1,
              const float* __restrict__ Wm_pi,
              const float* __restrict__ Wm_v,
              const float* __restrict__ Wt2,
              float* __restrict__ out)
{
    extern __shared__ float smf[];
    char* base = (char*)smf;
    const uint32_t su = (uint32_t)__cvta_generic_to_shared(smf);
    const int t = threadIdx.x;
    const int g0 = blockIdx.x * MT;
    int* icnt = (int*)(base + MISC_OFFB);

    zero_hw_tail(base, t);
    loadA_hw(base, t, 0, bm1, Wm_pi, Wm_v, Wt2);

    const size_t arow = (size_t)(g0 + (t >> 2))*DID + (t & 3)*8;
    const __half* aHi = g_obsHi + arow;
    const __half* aLo = g_obsLo + arow;

    float acc[2][8][4], hacc0[4][4], hacc1[4][4];
    ZERO_ACC(acc);
    #pragma unroll
    for (int m = 0; m < 4; ++m)
        #pragma unroll
        for (int e = 0; e < 4; ++e) { hacc0[m][e] = 0.f; hacc1[m][e] = 0.f; }

    __syncthreads();

    // B base for chunk g:  (g>>7) = net, ((g>>4)&7) = htile
    #define BA_HI(g) (g_wHiT + ((size_t)((g) >> 7)*HID + (((g) >> 4) & 7)*NTILE)*DID)
    #define BA_LO(g) (g_wLoT + ((size_t)((g) >> 7)*HID + (((g) >> 4) & 7)*NTILE)*DID)

    fill_chunk(su, t, 0, aHi, aLo, BA_HI(0), BA_LO(0));

    #pragma unroll 1
    for (int g = 0; g < 256; ++g) {
        CP_WAIT0();
        __syncthreads();
        if (g + 1 < 256)
            fill_chunk(su, t, g + 1, aHi, aLo, BA_HI(g + 1), BA_LO(g + 1));
        compute_chunk(su, t, g, acc);
        if ((g & 15) == 15) {
            const int tt = g >> 4;
            stage_h(base, acc, t);
            __syncthreads();
            if (tt < 8) head_mma(su, t, hacc0);
            else        head_mma(su, t, hacc1);
            __syncthreads();
            if (tt + 1 < 16) loadA_hw(base, t, tt + 1, bm1, Wm_pi, Wm_v, Wt2);
            ZERO_ACC(acc);
        }
    }
    #undef BA_HI
    #undef BA_LO

    store_hacc((float*)(base + FIN0_OFFB), t, hacc0);
    store_hacc((float*)(base + FIN1_OFFB), t, hacc1);

    int* s_cnt  = icnt + 64;
    int* s_base = icnt + 72;
    if (t < NOPT) s_cnt[t] = 0;
    __syncthreads();

    int myno = 0, mypos = 0;
    if (t < MT) {
        const float* fin0 = (const float*)(base + FIN0_OFFB) + t*FINSTR;
        const float* fin1 = (const float*)(base + FIN1_OFFB) + t*FINSTR;
        const int g = g0 + t;
        float lg[8];
        #pragma unroll
        for (int o = 0; o < 8; ++o) lg[o] = fin0[o];
        float mv = fin0[8];
        float m = lg[0]; int am = 0;
        #pragma unroll
        for (int o = 1; o < 8; ++o) if (lg[o] > m) { m = lg[o]; am = o; }
        float s = 0.f;
        #pragma unroll
        for (int o = 0; o < 8; ++o) s += expf(lg[o] - m);
        float lp = -logf(s);
        int eo = exec_opt[g];
        float tl = fin1[eo];
        float tp = 1.0f/(1.0f + expf(-tl));
        bool dn = (dones[g] != 0);
        bool term = dn || (tp > 0.5f);
        myno = term ? am : eo;
        out[3*B_AG + g] = (float)am;
        out[4*B_AG + g] = mv;
        out[5*B_AG + g] = lp;
        out[6*B_AG + g] = tp;
        mypos = atomicAdd(&s_cnt[myno], 1);
    }
    __syncthreads();
    if (t < NOPT) s_base[t] = atomicAdd(&g_opt_cnt[t], s_cnt[t]);
    __syncthreads();
    if (t < MT) g_opt_list[myno*B_AG + s_base[myno] + mypos] = g0 + t;
}

// ---------------------------------------------------------------------------
// Phase B: continuous 128-chunk stream (8 tiles x 16 chunks)
// ---------------------------------------------------------------------------
__global__ void __launch_bounds__(NT, 2)
phaseB_kernel(const float* __restrict__ b1,
              const float* __restrict__ Wpi,
              const float* __restrict__ Wv,
              float* __restrict__ out)
{
    const int opt   = blockIdx.y;
    const int start = blockIdx.x * MT;
    const int cnt   = g_opt_cnt[opt];
    if (start >= cnt) return;
    const int nvalid = min(MT, cnt - start);

    extern __shared__ float smf[];
    char* base = (char*)smf;
    const uint32_t su = (uint32_t)__cvta_generic_to_shared(smf);
    const int t = threadIdx.x;
    int* idx_s = (int*)(base + MISC_OFFB);

    zero_hw_tail(base, t);

    const float* bg   = b1  + (size_t)opt*HID;
    const float* wpig = Wpi + (size_t)opt*HID*NACT;
    const float* wvg  = Wv  + (size_t)opt*HID;

    // head weights + bias for tile 0
    {
        const float* wp = wpig + (size_t)t*NACT;
        #pragma unroll
        for (int a = 0; a < NACT; ++a) put_hw(base, a, t, wp[a]);
        put_hw(base, 16, t, wvg[t]);
        ((float*)(base + BIAS_OFFB))[t] = bg[t];
    }

    if (t < MT) {
        int src = opt*B_AG + start + ((t < nvalid) ? t : 0);
        idx_s[t] = g_opt_list[src];
    }
    __syncthreads();

    const size_t arow0 = (size_t)idx_s[t >> 2]*DID + (t & 3)*8;
    const size_t arow1 = (size_t)idx_s[(t >> 2) + 32]*DID + (t & 3)*8;
    // fill_chunk expects aHi + 32*DID for upper rows; here rows are gathered,
    // so pass two explicit pointers via a tiny wrapper below.
    const __half* aHi0 = g_obsHi + arow0;
    const __half* aHi1 = g_obsHi + arow1;
    const __half* aLo0 = g_obsLo + arow0;
    const __half* aLo1 = g_obsLo + arow1;

    float acc[2][8][4], hacc[4][4];
    ZERO_ACC(acc);
    #pragma unroll
    for (int m = 0; m < 4; ++m)
        #pragma unroll
        for (int e = 0; e < 4; ++e) hacc[m][e] = 0.f;

    const __half* wHiO = g_wHiT + (size_t)(2 + opt)*HID*DID;
    const __half* wLoO = g_wLoT + (size_t)(2 + opt)*HID*DID;

    #define FILLB(g) do {                                                    \
        const int _g = (g);                                                  \
        const uint32_t _drow = (uint32_t)((t >> 2)*80 + (t & 3)*16);         \
        const uint32_t _sb = su + ST(_g & 1) + _drow;                        \
        const int _ko = (_g & 15)*KCH;                                       \
        cp16(_sb + A_HI,        aHi0 + _ko);                                 \
        cp16(_sb + A_HI + 2560, aHi1 + _ko);                                 \
        cp16(_sb + A_LO,        aLo0 + _ko);                                 \
        cp16(_sb + A_LO + 2560, aLo1 + _ko);                                 \
        const size_t _boff = ((size_t)((_g >> 4)*NTILE + (t >> 2)))*DID      \
                           + (t & 3)*8 + _ko;                                \
        _Pragma("unroll")                                                    \
        for (int _j = 0; _j < 4; ++_j) {                                     \
            cp16(_sb + B_HI + _j*2560, wHiO + _boff + _j*32*DID);            \
            cp16(_sb + B_LO + _j*2560, wLoO + _boff + _j*32*DID);            \
        }                                                                    \
        CP_COMMIT();                                                         \
    } while (0)

    FILLB(0);

    #pragma unroll 1
    for (int g = 0; g < 128; ++g) {
        CP_WAIT0();
        __syncthreads();
        if (g + 1 < 128) FILLB(g + 1);
        compute_chunk(su, t, g, acc);
        if ((g & 15) == 15) {
            const int tt = g >> 4;
            stage_h(base, acc, t);
            __syncthreads();
            head_mma(su, t, hacc);
            __syncthreads();
            if (tt + 1 < 8) {
                const int hb = (tt + 1)*NTILE;
                const float* wp = wpig + (size_t)(hb + t)*NACT;
                #pragma unroll
                for (int a = 0; a < NACT; ++a) put_hw(base, a, t, wp[a]);
                put_hw(base, 16, t, wvg[hb + t]);
                ((float*)(base + BIAS_OFFB))[t] = bg[hb + t];
            }
            ZERO_ACC(acc);
        }
    }
    #undef FILLB

    store_hacc((float*)(base + FIN0_OFFB), t, hacc);
    __syncthreads();

    if (t < MT && t < nvalid) {
        const float* fin = (const float*)(base + FIN0_OFFB) + t*FINSTR;
        const int g = idx_s[t];
        float lg[16];
        #pragma unroll
        for (int a = 0; a < NACT; ++a) lg[a] = fin[a];
        float val = fin[16];
        float m = lg[0]; int am = 0;
        #pragma unroll
        for (int a = 1; a < NACT; ++a) if (lg[a] > m) { m = lg[a]; am = a; }
        float s = 0.f;
        #pragma unroll
        for (int a = 0; a < NACT; ++a) s += expf(lg[a] - m);
        float lp = -logf(s);
        out[          g] = (float)am;
        out[  B_AG +  g] = val;
        out[2*B_AG +  g] = lp;
    }
}

extern "C" void kernel_launch(void* const* d_in, const int* in_sizes, int n_in,
                              void* d_out, int out_size) {
    const float* obs      = (const float*)d_in[0];
    const int*   dones    = (const int*)  d_in[1];
    const int*   exec_opt = (const int*)  d_in[2];
    const float* Wm1      = (const float*)d_in[3];
    const float* bm1      = (const float*)d_in[4];
    const float* Wm_pi    = (const float*)d_in[5];
    const float* Wm_v     = (const float*)d_in[6];
    const float* Wt1      = (const float*)d_in[7];
    const float* Wt2      = (const float*)d_in[8];
    const float* W1       = (const float*)d_in[9];
    const float* b1       = (const float*)d_in[10];
    const float* Wpi      = (const float*)d_in[11];
    const float* Wv       = (const float*)d_in[12];
    float* out = (float*)d_out;

    cudaFuncSetAttribute(phaseA_kernel,
                         cudaFuncAttributeMaxDynamicSharedMemorySize, SMEM_BYTES);
    cudaFuncSetAttribute(phaseB_kernel,
                         cudaFuncAttributeMaxDynamicSharedMemorySize, SMEM_BYTES);

    convert_obs_kernel<<<(B_AG*DID)/(256*8), 256>>>(obs);
    dim3 gW(HID/32, DID/32, 10);
    convert_w_kernel<<<gW, dim3(32, 8)>>>(Wm1, Wt1, W1);
    phaseA_kernel<<<B_AG/MT, NT, SMEM_BYTES>>>(
        dones, exec_opt, bm1, Wm_pi, Wm_v, Wt2, out);
    dim3 gB(B_AG/MT, NOPT);
    phaseB_kernel<<<gB, NT, SMEM_BYTES>>>(b1, Wpi, Wv, out);
}